// round 6
// baseline (speedup 1.0000x reference)
#include <cuda_runtime.h>
#include <cstdint>

#define VOCAB   100000
#define NCODES  100000
#define NANC    8
#define EMB     128

// Scratch: projected embeddings P1 = W_emb @ W_att[0:128], P2 = W_emb @ W_att[128:256]
__device__ __align__(16) float g_P1[(size_t)VOCAB * EMB];
__device__ __align__(16) float g_P2[(size_t)VOCAB * EMB];

// Index-dtype flag: 1 if leaves/ancestors buffers are int64, 0 if int32.
__device__ int g_is64;

__device__ __forceinline__ float tanh_fast(float x) {
    float y;
    asm("tanh.approx.f32 %0, %1;" : "=f"(y) : "f"(x));
    return y;
}

// ---------------------------------------------------------------------------
// Dtype detection: genuine int64 indices (values in [0, VOCAB)) have every
// odd 32-bit word == 0. Random int32 indices make that essentially impossible
// across 400k words. Scans only the first NCODES*NANC 32-bit words, which is
// in-bounds for both interpretations. Overwrites g_is64 every call (graph-safe).
// ---------------------------------------------------------------------------
__global__ void detect_kernel(const unsigned int* __restrict__ w) {
    int nz = 0;
    for (int i = threadIdx.x; i < (NCODES * NANC) / 2; i += blockDim.x)
        nz |= (w[2 * i + 1] != 0u);
    nz = __syncthreads_or(nz);
    if (threadIdx.x == 0) g_is64 = (nz == 0);
}

// ---------------------------------------------------------------------------
// Projection GEMM: P[half] = W_emb[VOCAB,128] @ W_att[half*128 .. +128, :]
// BM=64, BN=128 (full), K=128 (full, in smem). 256 threads, f32x2 packed FMA.
// smem: As 64x128 (32KB) + Bs 128x128 (64KB) = 96KB dynamic.
// ---------------------------------------------------------------------------
__global__ __launch_bounds__(256, 2) void proj_kernel(const float* __restrict__ A,
                                                      const float* __restrict__ Watt) {
    extern __shared__ float sm[];
    float (*As)[128] = (float (*)[128])sm;               // [64][128]
    float (*Bs)[128] = (float (*)[128])(sm + 64 * 128);  // [128][128]

    const int half = blockIdx.y;
    const float* W = Watt + half * 128 * 128;
    float* P = half ? g_P2 : g_P1;
    const int m0 = blockIdx.x * 64;
    const int tid = threadIdx.x;

#pragma unroll
    for (int i = 0; i < 16; i++) {
        int idx = (tid + i * 256) * 4;
        *(float4*)((float*)Bs + idx) = __ldg((const float4*)(W + idx));
    }
#pragma unroll
    for (int i = 0; i < 8; i++) {
        int idx = (tid + i * 256) * 4;
        int m = idx >> 7;
        int k = idx & 127;
        int gm = m0 + m;
        if (gm >= VOCAB) gm = VOCAB - 1;
        *(float4*)(&As[m][k]) = __ldg((const float4*)(A + (size_t)gm * EMB + k));
    }
    __syncthreads();

    const int tx = tid & 15;
    const int ty = tid >> 4;
    const int mrow = ty * 4;
    const int ncol = tx * 8;

    unsigned long long acc[4][4];
#pragma unroll
    for (int i = 0; i < 4; i++)
#pragma unroll
        for (int j = 0; j < 4; j++) acc[i][j] = 0ull;

#pragma unroll 4
    for (int k0 = 0; k0 < 128; k0 += 4) {
        float4 av[4];
#pragma unroll
        for (int i = 0; i < 4; i++) av[i] = *(const float4*)&As[mrow + i][k0];
#pragma unroll
        for (int kk = 0; kk < 4; kk++) {
            ulonglong2 bq0 = *(const ulonglong2*)&Bs[k0 + kk][ncol];
            ulonglong2 bq1 = *(const ulonglong2*)&Bs[k0 + kk][ncol + 4];
#pragma unroll
            for (int i = 0; i < 4; i++) {
                float a = (kk == 0) ? av[i].x : (kk == 1) ? av[i].y
                         : (kk == 2) ? av[i].z : av[i].w;
                unsigned long long ap;
                asm("mov.b64 %0, {%1, %1};" : "=l"(ap) : "r"(__float_as_uint(a)));
                asm("fma.rn.f32x2 %0, %1, %2, %0;" : "+l"(acc[i][0]) : "l"(ap), "l"(bq0.x));
                asm("fma.rn.f32x2 %0, %1, %2, %0;" : "+l"(acc[i][1]) : "l"(ap), "l"(bq0.y));
                asm("fma.rn.f32x2 %0, %1, %2, %0;" : "+l"(acc[i][2]) : "l"(ap), "l"(bq1.x));
                asm("fma.rn.f32x2 %0, %1, %2, %0;" : "+l"(acc[i][3]) : "l"(ap), "l"(bq1.y));
            }
        }
    }

#pragma unroll
    for (int i = 0; i < 4; i++) {
        int gm = m0 + mrow + i;
        if (gm < VOCAB) {
            ulonglong2 v0, v1;
            v0.x = acc[i][0]; v0.y = acc[i][1];
            v1.x = acc[i][2]; v1.y = acc[i][3];
            *(ulonglong2*)(P + (size_t)gm * EMB + ncol)     = v0;
            *(ulonglong2*)(P + (size_t)gm * EMB + ncol + 4) = v1;
        }
    }
}

// ---------------------------------------------------------------------------
// Attention pass: one warp per code; lane l owns columns [4l, 4l+4).
// ---------------------------------------------------------------------------
__global__ __launch_bounds__(256) void attn_kernel(const float* __restrict__ W_emb,
                                                   const float* __restrict__ b_att,
                                                   const float* __restrict__ v_att,
                                                   const void* __restrict__ leaves,
                                                   const void* __restrict__ ancestors,
                                                   float* __restrict__ out) {
    const int warp = (blockIdx.x * blockDim.x + threadIdx.x) >> 5;
    const int lane = threadIdx.x & 31;
    if (warp >= NCODES) return;
    const int c = lane * 4;
    const int is64 = g_is64;

    const float4 bv = __ldg((const float4*)(b_att + c));
    const float4 vv = __ldg((const float4*)(v_att + c));

    float s[NANC];
    int aidx[NANC];

#pragma unroll
    for (int a = 0; a < NANC; a++) {
        const size_t off = (size_t)warp * NANC + a;
        int li, ai;
        if (is64) {
            li = (int)__ldg((const long long*)leaves + off);
            ai = (int)__ldg((const long long*)ancestors + off);
        } else {
            li = __ldg((const int*)leaves + off);
            ai = __ldg((const int*)ancestors + off);
        }
        // Defensive clamp: any misinterpretation becomes a rel_err, not a crash.
        li = min(max(li, 0), VOCAB - 1);
        ai = min(max(ai, 0), VOCAB - 1);
        aidx[a] = ai;

        const float4 p1 = __ldg((const float4*)(g_P1 + (size_t)li * EMB + c));
        const float4 p2 = __ldg((const float4*)(g_P2 + (size_t)ai * EMB + c));
        const float t0 = tanh_fast(p1.x + p2.x + bv.x);
        const float t1 = tanh_fast(p1.y + p2.y + bv.y);
        const float t2 = tanh_fast(p1.z + p2.z + bv.z);
        const float t3 = tanh_fast(p1.w + p2.w + bv.w);
        float d = t0 * vv.x + t1 * vv.y + t2 * vv.z + t3 * vv.w;
        d += __shfl_xor_sync(0xffffffffu, d, 16);
        d += __shfl_xor_sync(0xffffffffu, d, 8);
        d += __shfl_xor_sync(0xffffffffu, d, 4);
        d += __shfl_xor_sync(0xffffffffu, d, 2);
        d += __shfl_xor_sync(0xffffffffu, d, 1);
        s[a] = d;
    }

    float mx = s[0];
#pragma unroll
    for (int a = 1; a < NANC; a++) mx = fmaxf(mx, s[a]);
    float e[NANC];
    float sum = 0.0f;
#pragma unroll
    for (int a = 0; a < NANC; a++) { e[a] = __expf(s[a] - mx); sum += e[a]; }
    const float inv = 1.0f / sum;

    float4 accv = make_float4(0.f, 0.f, 0.f, 0.f);
#pragma unroll
    for (int a = 0; a < NANC; a++) {
        const float w = e[a] * inv;
        const float4 em = __ldg((const float4*)(W_emb + (size_t)aidx[a] * EMB + c));
        accv.x += w * em.x;
        accv.y += w * em.y;
        accv.z += w * em.z;
        accv.w += w * em.w;
    }
    *(float4*)(out + (size_t)warp * EMB + c) = accv;
}

extern "C" void kernel_launch(void* const* d_in, const int* in_sizes, int n_in,
                              void* d_out, int out_size) {
    // Size-based input identification (robust to metadata ordering).
    const float* W_emb = nullptr;
    const float* W_att = nullptr;
    const float* b_att = nullptr;
    const float* v_att = nullptr;
    const void*  leaves = nullptr;
    const void*  ancestors = nullptr;

    for (int i = 0; i < n_in; i++) {
        const int s = in_sizes[i];
        if (s == VOCAB * EMB)            { W_emb = (const float*)d_in[i]; }
        else if (s == 2 * EMB * EMB)     { W_att = (const float*)d_in[i]; }
        else if (s == EMB)               { if (!b_att) b_att = (const float*)d_in[i];
                                           else        v_att = (const float*)d_in[i]; }
        else if (s == NCODES * NANC)     { if (!leaves) leaves = d_in[i];
                                           else         ancestors = d_in[i]; }
    }
    // Positional fallback (reference dict order) if anything is missing.
    if (!W_emb)     W_emb     = (const float*)d_in[0];
    if (!W_att)     W_att     = (const float*)d_in[1];
    if (!b_att)     b_att     = (const float*)d_in[2];
    if (!v_att)     v_att     = (const float*)d_in[3];
    if (!leaves)    leaves    = d_in[4];
    if (!ancestors) ancestors = d_in[5];

    float* out = (float*)d_out;

    detect_kernel<<<1, 1024>>>((const unsigned int*)leaves);

    const int smem_bytes = (64 * 128 + 128 * 128) * (int)sizeof(float);  // 96KB
    cudaFuncSetAttribute(proj_kernel, cudaFuncAttributeMaxDynamicSharedMemorySize, smem_bytes);

    dim3 pg((VOCAB + 63) / 64, 2);
    proj_kernel<<<pg, 256, smem_bytes>>>(W_emb, W_att);

    const int total_threads = NCODES * 32;
    attn_kernel<<<(total_threads + 255) / 256, 256>>>(W_emb, b_att, v_att,
                                                      leaves, ancestors, out);
}

// round 7
// speedup vs baseline: 1.0040x; 1.0040x over previous
#include <cuda_runtime.h>
#include <cstdint>

#define VOCAB   100000
#define NCODES  100000
#define NANC    8
#define EMB     128

// Scratch: projected embeddings P1 = W_emb @ W_att[0:128], P2 = W_emb @ W_att[128:256]
__device__ __align__(16) float g_P1[(size_t)VOCAB * EMB];
__device__ __align__(16) float g_P2[(size_t)VOCAB * EMB];

// Index-dtype flag: 1 if leaves/ancestors buffers are int64, 0 if int32.
__device__ int g_is64;

__device__ __forceinline__ float tanh_fast(float x) {
    float y;
    asm("tanh.approx.f32 %0, %1;" : "=f"(y) : "f"(x));
    return y;
}

// ---------------------------------------------------------------------------
// Dtype detection: genuine int64 indices (values in [0, VOCAB)) have every
// odd 32-bit word == 0. Random int32 indices make that essentially impossible
// across 400k words. Scans only the first NCODES*NANC 32-bit words, which is
// in-bounds for both interpretations. Overwrites g_is64 every call (graph-safe).
// ---------------------------------------------------------------------------
__global__ void detect_kernel(const unsigned int* __restrict__ w) {
    int nz = 0;
    for (int i = threadIdx.x; i < (NCODES * NANC) / 2; i += blockDim.x)
        nz |= (w[2 * i + 1] != 0u);
    nz = __syncthreads_or(nz);
    if (threadIdx.x == 0) g_is64 = (nz == 0);
}

// ---------------------------------------------------------------------------
// Projection GEMM: P[half] = W_emb[VOCAB,128] @ W_att[half*128 .. +128, :]
// BM=64, BN=128 (full), K=128 (full, in smem). 256 threads, f32x2 packed FMA.
// smem: As 64x128 (32KB) + Bs 128x128 (64KB) = 96KB dynamic.
// ---------------------------------------------------------------------------
__global__ __launch_bounds__(256, 2) void proj_kernel(const float* __restrict__ A,
                                                      const float* __restrict__ Watt) {
    extern __shared__ float sm[];
    float (*As)[128] = (float (*)[128])sm;               // [64][128]
    float (*Bs)[128] = (float (*)[128])(sm + 64 * 128);  // [128][128]

    const int half = blockIdx.y;
    const float* W = Watt + half * 128 * 128;
    float* P = half ? g_P2 : g_P1;
    const int m0 = blockIdx.x * 64;
    const int tid = threadIdx.x;

#pragma unroll
    for (int i = 0; i < 16; i++) {
        int idx = (tid + i * 256) * 4;
        *(float4*)((float*)Bs + idx) = __ldg((const float4*)(W + idx));
    }
#pragma unroll
    for (int i = 0; i < 8; i++) {
        int idx = (tid + i * 256) * 4;
        int m = idx >> 7;
        int k = idx & 127;
        int gm = m0 + m;
        if (gm >= VOCAB) gm = VOCAB - 1;
        *(float4*)(&As[m][k]) = __ldg((const float4*)(A + (size_t)gm * EMB + k));
    }
    __syncthreads();

    const int tx = tid & 15;
    const int ty = tid >> 4;
    const int mrow = ty * 4;
    const int ncol = tx * 8;

    unsigned long long acc[4][4];
#pragma unroll
    for (int i = 0; i < 4; i++)
#pragma unroll
        for (int j = 0; j < 4; j++) acc[i][j] = 0ull;

#pragma unroll 4
    for (int k0 = 0; k0 < 128; k0 += 4) {
        float4 av[4];
#pragma unroll
        for (int i = 0; i < 4; i++) av[i] = *(const float4*)&As[mrow + i][k0];
#pragma unroll
        for (int kk = 0; kk < 4; kk++) {
            ulonglong2 bq0 = *(const ulonglong2*)&Bs[k0 + kk][ncol];
            ulonglong2 bq1 = *(const ulonglong2*)&Bs[k0 + kk][ncol + 4];
#pragma unroll
            for (int i = 0; i < 4; i++) {
                float a = (kk == 0) ? av[i].x : (kk == 1) ? av[i].y
                         : (kk == 2) ? av[i].z : av[i].w;
                unsigned long long ap;
                asm("mov.b64 %0, {%1, %1};" : "=l"(ap) : "r"(__float_as_uint(a)));
                asm("fma.rn.f32x2 %0, %1, %2, %0;" : "+l"(acc[i][0]) : "l"(ap), "l"(bq0.x));
                asm("fma.rn.f32x2 %0, %1, %2, %0;" : "+l"(acc[i][1]) : "l"(ap), "l"(bq0.y));
                asm("fma.rn.f32x2 %0, %1, %2, %0;" : "+l"(acc[i][2]) : "l"(ap), "l"(bq1.x));
                asm("fma.rn.f32x2 %0, %1, %2, %0;" : "+l"(acc[i][3]) : "l"(ap), "l"(bq1.y));
            }
        }
    }

#pragma unroll
    for (int i = 0; i < 4; i++) {
        int gm = m0 + mrow + i;
        if (gm < VOCAB) {
            ulonglong2 v0, v1;
            v0.x = acc[i][0]; v0.y = acc[i][1];
            v1.x = acc[i][2]; v1.y = acc[i][3];
            *(ulonglong2*)(P + (size_t)gm * EMB + ncol)     = v0;
            *(ulonglong2*)(P + (size_t)gm * EMB + ncol + 4) = v1;
        }
    }
}

// ---------------------------------------------------------------------------
// Attention pass: one warp per code; lane l owns columns [4l, 4l+4).
// ---------------------------------------------------------------------------
__global__ __launch_bounds__(256) void attn_kernel(const float* __restrict__ W_emb,
                                                   const float* __restrict__ b_att,
                                                   const float* __restrict__ v_att,
                                                   const void* __restrict__ leaves,
                                                   const void* __restrict__ ancestors,
                                                   float* __restrict__ out) {
    const int warp = (blockIdx.x * blockDim.x + threadIdx.x) >> 5;
    const int lane = threadIdx.x & 31;
    if (warp >= NCODES) return;
    const int c = lane * 4;
    const int is64 = g_is64;

    const float4 bv = __ldg((const float4*)(b_att + c));
    const float4 vv = __ldg((const float4*)(v_att + c));

    float s[NANC];
    int aidx[NANC];

#pragma unroll
    for (int a = 0; a < NANC; a++) {
        const size_t off = (size_t)warp * NANC + a;
        int li, ai;
        if (is64) {
            li = (int)__ldg((const long long*)leaves + off);
            ai = (int)__ldg((const long long*)ancestors + off);
        } else {
            li = __ldg((const int*)leaves + off);
            ai = __ldg((const int*)ancestors + off);
        }
        // Defensive clamp: any misinterpretation becomes a rel_err, not a crash.
        li = min(max(li, 0), VOCAB - 1);
        ai = min(max(ai, 0), VOCAB - 1);
        aidx[a] = ai;

        const float4 p1 = __ldg((const float4*)(g_P1 + (size_t)li * EMB + c));
        const float4 p2 = __ldg((const float4*)(g_P2 + (size_t)ai * EMB + c));
        const float t0 = tanh_fast(p1.x + p2.x + bv.x);
        const float t1 = tanh_fast(p1.y + p2.y + bv.y);
        const float t2 = tanh_fast(p1.z + p2.z + bv.z);
        const float t3 = tanh_fast(p1.w + p2.w + bv.w);
        float d = t0 * vv.x + t1 * vv.y + t2 * vv.z + t3 * vv.w;
        d += __shfl_xor_sync(0xffffffffu, d, 16);
        d += __shfl_xor_sync(0xffffffffu, d, 8);
        d += __shfl_xor_sync(0xffffffffu, d, 4);
        d += __shfl_xor_sync(0xffffffffu, d, 2);
        d += __shfl_xor_sync(0xffffffffu, d, 1);
        s[a] = d;
    }

    float mx = s[0];
#pragma unroll
    for (int a = 1; a < NANC; a++) mx = fmaxf(mx, s[a]);
    float e[NANC];
    float sum = 0.0f;
#pragma unroll
    for (int a = 0; a < NANC; a++) { e[a] = __expf(s[a] - mx); sum += e[a]; }
    const float inv = 1.0f / sum;

    float4 accv = make_float4(0.f, 0.f, 0.f, 0.f);
#pragma unroll
    for (int a = 0; a < NANC; a++) {
        const float w = e[a] * inv;
        const float4 em = __ldg((const float4*)(W_emb + (size_t)aidx[a] * EMB + c));
        accv.x += w * em.x;
        accv.y += w * em.y;
        accv.z += w * em.z;
        accv.w += w * em.w;
    }
    *(float4*)(out + (size_t)warp * EMB + c) = accv;
}

extern "C" void kernel_launch(void* const* d_in, const int* in_sizes, int n_in,
                              void* d_out, int out_size) {
    // Size-based input identification (robust to metadata ordering).
    const float* W_emb = nullptr;
    const float* W_att = nullptr;
    const float* b_att = nullptr;
    const float* v_att = nullptr;
    const void*  leaves = nullptr;
    const void*  ancestors = nullptr;

    for (int i = 0; i < n_in; i++) {
        const int s = in_sizes[i];
        if (s == VOCAB * EMB)            { W_emb = (const float*)d_in[i]; }
        else if (s == 2 * EMB * EMB)     { W_att = (const float*)d_in[i]; }
        else if (s == EMB)               { if (!b_att) b_att = (const float*)d_in[i];
                                           else        v_att = (const float*)d_in[i]; }
        else if (s == NCODES * NANC)     { if (!leaves) leaves = d_in[i];
                                           else         ancestors = d_in[i]; }
    }
    // Positional fallback (reference dict order) if anything is missing.
    if (!W_emb)     W_emb     = (const float*)d_in[0];
    if (!W_att)     W_att     = (const float*)d_in[1];
    if (!b_att)     b_att     = (const float*)d_in[2];
    if (!v_att)     v_att     = (const float*)d_in[3];
    if (!leaves)    leaves    = d_in[4];
    if (!ancestors) ancestors = d_in[5];

    float* out = (float*)d_out;

    detect_kernel<<<1, 1024>>>((const unsigned int*)leaves);

    const int smem_bytes = (64 * 128 + 128 * 128) * (int)sizeof(float);  // 96KB
    cudaFuncSetAttribute(proj_kernel, cudaFuncAttributeMaxDynamicSharedMemorySize, smem_bytes);

    dim3 pg((VOCAB + 63) / 64, 2);
    proj_kernel<<<pg, 256, smem_bytes>>>(W_emb, W_att);

    const int total_threads = NCODES * 32;
    attn_kernel<<<(total_threads + 255) / 256, 256>>>(W_emb, b_att, v_att,
                                                      leaves, ancestors, out);
}

// round 8
// speedup vs baseline: 1.1200x; 1.1155x over previous
#include <cuda_runtime.h>
#include <cstdint>

#define VOCAB   100000
#define NCODES  100000
#define NANC    8
#define EMB     128

// Scratch: projected embeddings P1 = W_emb @ W_att[0:128], P2 = W_emb @ W_att[128:256]
__device__ __align__(16) float g_P1[(size_t)VOCAB * EMB];
__device__ __align__(16) float g_P2[(size_t)VOCAB * EMB];

// Index-dtype flag: 1 if leaves/ancestors buffers are int64, 0 if int32.
__device__ int g_is64;

__device__ __forceinline__ float tanh_fast(float x) {
    float y;
    asm("tanh.approx.f32 %0, %1;" : "=f"(y) : "f"(x));
    return y;
}

// ---------------------------------------------------------------------------
// Dtype detection, SAMPLED: genuine int64 indices (< VOCAB) have every odd
// 32-bit word == 0. For int32 data the odd words are random indices in
// [0, VOCAB): P(one sample == 0) = 1e-5, so P(all ~6250 strided samples == 0)
// is numerically zero. Single block, ~6 strided loads/thread: ~4us.
// ---------------------------------------------------------------------------
__global__ void detect_kernel(const unsigned int* __restrict__ w) {
    const int half = (NCODES * NANC) / 2;   // # of odd words in int64 view
    int nz = 0;
    // stride 64 over odd-word index space -> 6250 samples spread over buffer
    for (int i = threadIdx.x; i < half / 64; i += blockDim.x)
        nz |= (w[2 * (i * 64) + 1] != 0u);
    nz = __syncthreads_or(nz);
    if (threadIdx.x == 0) g_is64 = (nz == 0);
}

// ---------------------------------------------------------------------------
// Projection GEMM: P[half] = W_emb[VOCAB,128] @ W_att[half*128 .. +128, :]
// BM=64, BN=128 (full), K=128 (full, in smem). 256 threads, f32x2 packed FMA.
// FMA-issue bound (~100us); smem traffic is not the wall (broadcast dedup).
// ---------------------------------------------------------------------------
__global__ __launch_bounds__(256, 2) void proj_kernel(const float* __restrict__ A,
                                                      const float* __restrict__ Watt) {
    extern __shared__ float sm[];
    float (*As)[128] = (float (*)[128])sm;               // [64][128]
    float (*Bs)[128] = (float (*)[128])(sm + 64 * 128);  // [128][128]

    const int half = blockIdx.y;
    const float* W = Watt + half * 128 * 128;
    float* P = half ? g_P2 : g_P1;
    const int m0 = blockIdx.x * 64;
    const int tid = threadIdx.x;

#pragma unroll
    for (int i = 0; i < 16; i++) {
        int idx = (tid + i * 256) * 4;
        *(float4*)((float*)Bs + idx) = __ldg((const float4*)(W + idx));
    }
#pragma unroll
    for (int i = 0; i < 8; i++) {
        int idx = (tid + i * 256) * 4;
        int m = idx >> 7;
        int k = idx & 127;
        int gm = m0 + m;
        if (gm >= VOCAB) gm = VOCAB - 1;
        *(float4*)(&As[m][k]) = __ldg((const float4*)(A + (size_t)gm * EMB + k));
    }
    __syncthreads();

    const int tx = tid & 15;
    const int ty = tid >> 4;
    const int mrow = ty * 4;
    const int ncol = tx * 8;

    unsigned long long acc[4][4];
#pragma unroll
    for (int i = 0; i < 4; i++)
#pragma unroll
        for (int j = 0; j < 4; j++) acc[i][j] = 0ull;

#pragma unroll 4
    for (int k0 = 0; k0 < 128; k0 += 4) {
        float4 av[4];
#pragma unroll
        for (int i = 0; i < 4; i++) av[i] = *(const float4*)&As[mrow + i][k0];
#pragma unroll
        for (int kk = 0; kk < 4; kk++) {
            ulonglong2 bq0 = *(const ulonglong2*)&Bs[k0 + kk][ncol];
            ulonglong2 bq1 = *(const ulonglong2*)&Bs[k0 + kk][ncol + 4];
#pragma unroll
            for (int i = 0; i < 4; i++) {
                float a = (kk == 0) ? av[i].x : (kk == 1) ? av[i].y
                         : (kk == 2) ? av[i].z : av[i].w;
                unsigned long long ap;
                asm("mov.b64 %0, {%1, %1};" : "=l"(ap) : "r"(__float_as_uint(a)));
                asm("fma.rn.f32x2 %0, %1, %2, %0;" : "+l"(acc[i][0]) : "l"(ap), "l"(bq0.x));
                asm("fma.rn.f32x2 %0, %1, %2, %0;" : "+l"(acc[i][1]) : "l"(ap), "l"(bq0.y));
                asm("fma.rn.f32x2 %0, %1, %2, %0;" : "+l"(acc[i][2]) : "l"(ap), "l"(bq1.x));
                asm("fma.rn.f32x2 %0, %1, %2, %0;" : "+l"(acc[i][3]) : "l"(ap), "l"(bq1.y));
            }
        }
    }

#pragma unroll
    for (int i = 0; i < 4; i++) {
        int gm = m0 + mrow + i;
        if (gm < VOCAB) {
            ulonglong2 v0, v1;
            v0.x = acc[i][0]; v0.y = acc[i][1];
            v1.x = acc[i][2]; v1.y = acc[i][3];
            *(ulonglong2*)(P + (size_t)gm * EMB + ncol)     = v0;
            *(ulonglong2*)(P + (size_t)gm * EMB + ncol + 4) = v1;
        }
    }
}

// ---------------------------------------------------------------------------
// Attention pass: one warp per code; lane l owns columns [4l, 4l+4).
// Restructured for memory-level parallelism:
//   phase 1: load all 16 indices
//   phase 2: issue ALL 16 P1/P2 gathers (no compute interleaved)
//   phase 3: tanh + per-lane dots (MUFU work overlaps outstanding loads)
//   phase 4: issue ALL 8 W_emb gathers (independent of scores)
//   phase 5: 8 butterfly reductions, stage-interleaved (parallel chains)
//   phase 6: softmax + weighted sum of em[] (gathers have landed by now)
// ---------------------------------------------------------------------------
__global__ __launch_bounds__(256) void attn_kernel(const float* __restrict__ W_emb,
                                                   const float* __restrict__ b_att,
                                                   const float* __restrict__ v_att,
                                                   const void* __restrict__ leaves,
                                                   const void* __restrict__ ancestors,
                                                   float* __restrict__ out) {
    const int warp = (blockIdx.x * blockDim.x + threadIdx.x) >> 5;
    const int lane = threadIdx.x & 31;
    if (warp >= NCODES) return;
    const int c = lane * 4;
    const int is64 = g_is64;

    const float4 bv = __ldg((const float4*)(b_att + c));
    const float4 vv = __ldg((const float4*)(v_att + c));

    // ---- phase 1: indices ----
    int li[NANC], ai[NANC];
    const size_t base = (size_t)warp * NANC;
    if (is64) {
#pragma unroll
        for (int a = 0; a < NANC; a++) {
            li[a] = (int)__ldg((const long long*)leaves + base + a);
            ai[a] = (int)__ldg((const long long*)ancestors + base + a);
        }
    } else {
#pragma unroll
        for (int a = 0; a < NANC; a++) {
            li[a] = __ldg((const int*)leaves + base + a);
            ai[a] = __ldg((const int*)ancestors + base + a);
        }
    }
#pragma unroll
    for (int a = 0; a < NANC; a++) {
        li[a] = min(max(li[a], 0), VOCAB - 1);
        ai[a] = min(max(ai[a], 0), VOCAB - 1);
    }

    // ---- phase 2: batch all P1/P2 gathers ----
    float4 p1v[NANC], p2v[NANC];
#pragma unroll
    for (int a = 0; a < NANC; a++)
        p1v[a] = __ldg((const float4*)(g_P1 + (size_t)li[a] * EMB + c));
#pragma unroll
    for (int a = 0; a < NANC; a++)
        p2v[a] = __ldg((const float4*)(g_P2 + (size_t)ai[a] * EMB + c));

    // ---- phase 3: tanh + per-lane partial dots ----
    float d[NANC];
#pragma unroll
    for (int a = 0; a < NANC; a++) {
        const float t0 = tanh_fast(p1v[a].x + p2v[a].x + bv.x);
        const float t1 = tanh_fast(p1v[a].y + p2v[a].y + bv.y);
        const float t2 = tanh_fast(p1v[a].z + p2v[a].z + bv.z);
        const float t3 = tanh_fast(p1v[a].w + p2v[a].w + bv.w);
        d[a] = t0 * vv.x + t1 * vv.y + t2 * vv.z + t3 * vv.w;
    }

    // ---- phase 4: batch W_emb gathers (overlap with reduction latency) ----
    float4 em[NANC];
#pragma unroll
    for (int a = 0; a < NANC; a++)
        em[a] = __ldg((const float4*)(W_emb + (size_t)ai[a] * EMB + c));

    // ---- phase 5: parallel butterfly reductions across all 8 scores ----
#pragma unroll
    for (int m = 16; m >= 1; m >>= 1) {
#pragma unroll
        for (int a = 0; a < NANC; a++)
            d[a] += __shfl_xor_sync(0xffffffffu, d[a], m);
    }

    // ---- phase 6: softmax + weighted sum ----
    float mx = d[0];
#pragma unroll
    for (int a = 1; a < NANC; a++) mx = fmaxf(mx, d[a]);
    float sum = 0.0f;
#pragma unroll
    for (int a = 0; a < NANC; a++) { d[a] = __expf(d[a] - mx); sum += d[a]; }
    const float inv = 1.0f / sum;

    float4 accv = make_float4(0.f, 0.f, 0.f, 0.f);
#pragma unroll
    for (int a = 0; a < NANC; a++) {
        const float w = d[a] * inv;
        accv.x += w * em[a].x;
        accv.y += w * em[a].y;
        accv.z += w * em[a].z;
        accv.w += w * em[a].w;
    }
    *(float4*)(out + (size_t)warp * EMB + c) = accv;
}

extern "C" void kernel_launch(void* const* d_in, const int* in_sizes, int n_in,
                              void* d_out, int out_size) {
    // Size-based input identification (robust to metadata ordering).
    const float* W_emb = nullptr;
    const float* W_att = nullptr;
    const float* b_att = nullptr;
    const float* v_att = nullptr;
    const void*  leaves = nullptr;
    const void*  ancestors = nullptr;

    for (int i = 0; i < n_in; i++) {
        const int s = in_sizes[i];
        if (s == VOCAB * EMB)            { W_emb = (const float*)d_in[i]; }
        else if (s == 2 * EMB * EMB)     { W_att = (const float*)d_in[i]; }
        else if (s == EMB)               { if (!b_att) b_att = (const float*)d_in[i];
                                           else        v_att = (const float*)d_in[i]; }
        else if (s == NCODES * NANC)     { if (!leaves) leaves = d_in[i];
                                           else         ancestors = d_in[i]; }
    }
    if (!W_emb)     W_emb     = (const float*)d_in[0];
    if (!W_att)     W_att     = (const float*)d_in[1];
    if (!b_att)     b_att     = (const float*)d_in[2];
    if (!v_att)     v_att     = (const float*)d_in[3];
    if (!leaves)    leaves    = d_in[4];
    if (!ancestors) ancestors = d_in[5];

    float* out = (float*)d_out;

    detect_kernel<<<1, 1024>>>((const unsigned int*)leaves);

    const int smem_bytes = (64 * 128 + 128 * 128) * (int)sizeof(float);  // 96KB
    cudaFuncSetAttribute(proj_kernel, cudaFuncAttributeMaxDynamicSharedMemorySize, smem_bytes);

    dim3 pg((VOCAB + 63) / 64, 2);
    proj_kernel<<<pg, 256, smem_bytes>>>(W_emb, W_att);

    const int total_threads = NCODES * 32;
    attn_kernel<<<(total_threads + 255) / 256, 256>>>(W_emb, b_att, v_att,
                                                      leaves, ancestors, out);
}

// round 9
// speedup vs baseline: 1.2785x; 1.1416x over previous
#include <cuda_runtime.h>
#include <cuda_bf16.h>
#include <cstdint>

#define VOCAB   100000
#define NCODES  100000
#define NANC    8
#define EMB     128

// Scratch: projected embeddings in bf16 (halves gather traffic; working set
// P1+P2+W_emb = 26+26+51 = 103MB < 126MB L2).
// P1 = W_emb @ W_att[0:128], P2 = W_emb @ W_att[128:256]
__device__ __align__(16) __nv_bfloat16 g_P1[(size_t)VOCAB * EMB];
__device__ __align__(16) __nv_bfloat16 g_P2[(size_t)VOCAB * EMB];

// Index-dtype flag: 1 if leaves/ancestors buffers are int64, 0 if int32.
__device__ int g_is64;

__device__ __forceinline__ float tanh_fast(float x) {
    float y;
    asm("tanh.approx.f32 %0, %1;" : "=f"(y) : "f"(x));
    return y;
}

// ---------------------------------------------------------------------------
// Dtype detection, SAMPLED (2048 spread samples): genuine int64 indices
// (< VOCAB) have every odd 32-bit word == 0; for int32 data each sampled word
// is a random index, zero w.p. 1e-5 -> P(all 2048 zero) ~ 0. ~2.5us.
// ---------------------------------------------------------------------------
__global__ void detect_kernel(const unsigned int* __restrict__ w) {
    const int half = (NCODES * NANC) / 2;      // 400000 odd words in int64 view
    const int stride = half / 2048;            // 195
    int nz = 0;
#pragma unroll
    for (int j = 0; j < 2; j++) {
        int k = (threadIdx.x + j * 1024) * stride;
        nz |= (__ldg(w + 2 * k + 1) != 0u);
    }
    nz = __syncthreads_or(nz);
    if (threadIdx.x == 0) g_is64 = (nz == 0);
}

// ---------------------------------------------------------------------------
// Projection GEMM: P[half] = W_emb[VOCAB,128] @ W_att[half*128 .. +128, :]
// BM=64, BN=128 (full), K=128 (full, in smem). 256 threads, f32x2 packed FMA.
// Math in f32; result rounded to bf16 at store.
// ---------------------------------------------------------------------------
__global__ __launch_bounds__(256, 2) void proj_kernel(const float* __restrict__ A,
                                                      const float* __restrict__ Watt) {
    extern __shared__ float sm[];
    float (*As)[128] = (float (*)[128])sm;               // [64][128]
    float (*Bs)[128] = (float (*)[128])(sm + 64 * 128);  // [128][128]

    const int half = blockIdx.y;
    const float* W = Watt + half * 128 * 128;
    __nv_bfloat16* P = half ? g_P2 : g_P1;
    const int m0 = blockIdx.x * 64;
    const int tid = threadIdx.x;

#pragma unroll
    for (int i = 0; i < 16; i++) {
        int idx = (tid + i * 256) * 4;
        *(float4*)((float*)Bs + idx) = __ldg((const float4*)(W + idx));
    }
#pragma unroll
    for (int i = 0; i < 8; i++) {
        int idx = (tid + i * 256) * 4;
        int m = idx >> 7;
        int k = idx & 127;
        int gm = m0 + m;
        if (gm >= VOCAB) gm = VOCAB - 1;
        *(float4*)(&As[m][k]) = __ldg((const float4*)(A + (size_t)gm * EMB + k));
    }
    __syncthreads();

    const int tx = tid & 15;
    const int ty = tid >> 4;
    const int mrow = ty * 4;
    const int ncol = tx * 8;

    unsigned long long acc[4][4];
#pragma unroll
    for (int i = 0; i < 4; i++)
#pragma unroll
        for (int j = 0; j < 4; j++) acc[i][j] = 0ull;

#pragma unroll 4
    for (int k0 = 0; k0 < 128; k0 += 4) {
        float4 av[4];
#pragma unroll
        for (int i = 0; i < 4; i++) av[i] = *(const float4*)&As[mrow + i][k0];
#pragma unroll
        for (int kk = 0; kk < 4; kk++) {
            ulonglong2 bq0 = *(const ulonglong2*)&Bs[k0 + kk][ncol];
            ulonglong2 bq1 = *(const ulonglong2*)&Bs[k0 + kk][ncol + 4];
#pragma unroll
            for (int i = 0; i < 4; i++) {
                float a = (kk == 0) ? av[i].x : (kk == 1) ? av[i].y
                         : (kk == 2) ? av[i].z : av[i].w;
                unsigned long long ap;
                asm("mov.b64 %0, {%1, %1};" : "=l"(ap) : "r"(__float_as_uint(a)));
                asm("fma.rn.f32x2 %0, %1, %2, %0;" : "+l"(acc[i][0]) : "l"(ap), "l"(bq0.x));
                asm("fma.rn.f32x2 %0, %1, %2, %0;" : "+l"(acc[i][1]) : "l"(ap), "l"(bq0.y));
                asm("fma.rn.f32x2 %0, %1, %2, %0;" : "+l"(acc[i][2]) : "l"(ap), "l"(bq1.x));
                asm("fma.rn.f32x2 %0, %1, %2, %0;" : "+l"(acc[i][3]) : "l"(ap), "l"(bq1.y));
            }
        }
    }

    // Store: convert 8 f32 (4 f32x2 pairs) -> 4 bf16x2 words -> one 16B store.
#pragma unroll
    for (int i = 0; i < 4; i++) {
        int gm = m0 + mrow + i;
        if (gm < VOCAB) {
            uint4 ov;
            unsigned* po = (unsigned*)&ov;
#pragma unroll
            for (int j = 0; j < 4; j++) {
                float lo = __uint_as_float((unsigned)(acc[i][j] & 0xffffffffull));
                float hi = __uint_as_float((unsigned)(acc[i][j] >> 32));
                // cvt.rn.bf16x2.f32 d, a, b  ->  d.lo = cvt(b), d.hi = cvt(a)
                asm("cvt.rn.bf16x2.f32 %0, %1, %2;" : "=r"(po[j]) : "f"(hi), "f"(lo));
            }
            *(uint4*)(P + (size_t)gm * EMB + ncol) = ov;
        }
    }
}

// ---------------------------------------------------------------------------
// Attention pass: one warp per code; lane l owns columns [4l, 4l+4).
// P1/P2 rows are bf16 (8B/lane), W_emb rows f32 (16B/lane).
// ---------------------------------------------------------------------------
__global__ __launch_bounds__(256) void attn_kernel(const float* __restrict__ W_emb,
                                                   const float* __restrict__ b_att,
                                                   const float* __restrict__ v_att,
                                                   const void* __restrict__ leaves,
                                                   const void* __restrict__ ancestors,
                                                   float* __restrict__ out) {
    const int warp = (blockIdx.x * blockDim.x + threadIdx.x) >> 5;
    const int lane = threadIdx.x & 31;
    if (warp >= NCODES) return;
    const int c = lane * 4;
    const int is64 = g_is64;

    const float4 bv = __ldg((const float4*)(b_att + c));
    const float4 vv = __ldg((const float4*)(v_att + c));

    // ---- indices ----
    int li[NANC], ai[NANC];
    const size_t base = (size_t)warp * NANC;
    if (is64) {
#pragma unroll
        for (int a = 0; a < NANC; a++) {
            li[a] = (int)__ldg((const long long*)leaves + base + a);
            ai[a] = (int)__ldg((const long long*)ancestors + base + a);
        }
    } else {
#pragma unroll
        for (int a = 0; a < NANC; a++) {
            li[a] = __ldg((const int*)leaves + base + a);
            ai[a] = __ldg((const int*)ancestors + base + a);
        }
    }
#pragma unroll
    for (int a = 0; a < NANC; a++) {
        li[a] = min(max(li[a], 0), VOCAB - 1);
        ai[a] = min(max(ai[a], 0), VOCAB - 1);
    }

    // ---- batch all P1/P2 gathers (bf16: uint2 = 4 values/lane) ----
    uint2 p1v[NANC], p2v[NANC];
#pragma unroll
    for (int a = 0; a < NANC; a++)
        p1v[a] = __ldg((const uint2*)(g_P1 + (size_t)li[a] * EMB + c));
#pragma unroll
    for (int a = 0; a < NANC; a++)
        p2v[a] = __ldg((const uint2*)(g_P2 + (size_t)ai[a] * EMB + c));

    // ---- batch W_emb gathers (independent of scores) ----
    float4 em[NANC];
#pragma unroll
    for (int a = 0; a < NANC; a++)
        em[a] = __ldg((const float4*)(W_emb + (size_t)ai[a] * EMB + c));

    // ---- tanh + per-lane partial dots ----
    float d[NANC];
#pragma unroll
    for (int a = 0; a < NANC; a++) {
        const float2 p1a = __bfloat1622float2(*(const __nv_bfloat162*)&p1v[a].x);
        const float2 p1b = __bfloat1622float2(*(const __nv_bfloat162*)&p1v[a].y);
        const float2 p2a = __bfloat1622float2(*(const __nv_bfloat162*)&p2v[a].x);
        const float2 p2b = __bfloat1622float2(*(const __nv_bfloat162*)&p2v[a].y);
        const float t0 = tanh_fast(p1a.x + p2a.x + bv.x);
        const float t1 = tanh_fast(p1a.y + p2a.y + bv.y);
        const float t2 = tanh_fast(p1b.x + p2b.x + bv.z);
        const float t3 = tanh_fast(p1b.y + p2b.y + bv.w);
        d[a] = t0 * vv.x + t1 * vv.y + t2 * vv.z + t3 * vv.w;
    }

    // ---- parallel butterfly reductions across all 8 scores ----
#pragma unroll
    for (int m = 16; m >= 1; m >>= 1) {
#pragma unroll
        for (int a = 0; a < NANC; a++)
            d[a] += __shfl_xor_sync(0xffffffffu, d[a], m);
    }

    // ---- softmax + weighted sum ----
    float mx = d[0];
#pragma unroll
    for (int a = 1; a < NANC; a++) mx = fmaxf(mx, d[a]);
    float sum = 0.0f;
#pragma unroll
    for (int a = 0; a < NANC; a++) { d[a] = __expf(d[a] - mx); sum += d[a]; }
    const float inv = 1.0f / sum;

    float4 accv = make_float4(0.f, 0.f, 0.f, 0.f);
#pragma unroll
    for (int a = 0; a < NANC; a++) {
        const float w = d[a] * inv;
        accv.x += w * em[a].x;
        accv.y += w * em[a].y;
        accv.z += w * em[a].z;
        accv.w += w * em[a].w;
    }
    *(float4*)(out + (size_t)warp * EMB + c) = accv;
}

extern "C" void kernel_launch(void* const* d_in, const int* in_sizes, int n_in,
                              void* d_out, int out_size) {
    // Size-based input identification (robust to metadata ordering).
    const float* W_emb = nullptr;
    const float* W_att = nullptr;
    const float* b_att = nullptr;
    const float* v_att = nullptr;
    const void*  leaves = nullptr;
    const void*  ancestors = nullptr;

    for (int i = 0; i < n_in; i++) {
        const int s = in_sizes[i];
        if (s == VOCAB * EMB)            { W_emb = (const float*)d_in[i]; }
        else if (s == 2 * EMB * EMB)     { W_att = (const float*)d_in[i]; }
        else if (s == EMB)               { if (!b_att) b_att = (const float*)d_in[i];
                                           else        v_att = (const float*)d_in[i]; }
        else if (s == NCODES * NANC)     { if (!leaves) leaves = d_in[i];
                                           else         ancestors = d_in[i]; }
    }
    if (!W_emb)     W_emb     = (const float*)d_in[0];
    if (!W_att)     W_att     = (const float*)d_in[1];
    if (!b_att)     b_att     = (const float*)d_in[2];
    if (!v_att)     v_att     = (const float*)d_in[3];
    if (!leaves)    leaves    = d_in[4];
    if (!ancestors) ancestors = d_in[5];

    float* out = (float*)d_out;

    detect_kernel<<<1, 1024>>>((const unsigned int*)leaves);

    const int smem_bytes = (64 * 128 + 128 * 128) * (int)sizeof(float);  // 96KB
    cudaFuncSetAttribute(proj_kernel, cudaFuncAttributeMaxDynamicSharedMemorySize, smem_bytes);

    dim3 pg((VOCAB + 63) / 64, 2);
    proj_kernel<<<pg, 256, smem_bytes>>>(W_emb, W_att);

    const int total_threads = NCODES * 32;
    attn_kernel<<<(total_threads + 255) / 256, 256>>>(W_emb, b_att, v_att,
                                                      leaves, ancestors, out);
}

// round 10
// speedup vs baseline: 1.2947x; 1.0126x over previous
#include <cuda_runtime.h>
#include <cuda_bf16.h>
#include <cstdint>

#define VOCAB   100000
#define NCODES  100000
#define NANC    8
#define EMB     128

// Scratch: projected embeddings in bf16 (halves gather traffic; working set
// P1+P2+W_emb = 26+26+51 = 103MB < 126MB L2).
// P1 = W_emb @ W_att[0:128], P2 = W_emb @ W_att[128:256]
__device__ __align__(16) __nv_bfloat16 g_P1[(size_t)VOCAB * EMB];
__device__ __align__(16) __nv_bfloat16 g_P2[(size_t)VOCAB * EMB];

// Index-dtype flag: 1 if leaves/ancestors buffers are int64, 0 if int32.
__device__ int g_is64;

__device__ __forceinline__ float tanh_fast(float x) {
    float y;
    asm("tanh.approx.f32 %0, %1;" : "=f"(y) : "f"(x));
    return y;
}

// ---------------------------------------------------------------------------
// Dtype detection, SAMPLED (2048 spread samples): genuine int64 indices
// (< VOCAB) have every odd 32-bit word == 0; for int32 data each sampled word
// is a random index, zero w.p. 1e-5 -> P(all 2048 zero) ~ 0.
// ---------------------------------------------------------------------------
__global__ void detect_kernel(const unsigned int* __restrict__ w) {
    const int half = (NCODES * NANC) / 2;      // 400000 odd words in int64 view
    const int stride = half / 2048;            // 195
    int nz = 0;
#pragma unroll
    for (int j = 0; j < 2; j++) {
        int k = (threadIdx.x + j * 1024) * stride;
        nz |= (__ldg(w + 2 * k + 1) != 0u);
    }
    nz = __syncthreads_or(nz);
    if (threadIdx.x == 0) g_is64 = (nz == 0);
}

// ---------------------------------------------------------------------------
// Projection GEMM: P[half] = W_emb[VOCAB,128] @ W_att[half*128 .. +128, :]
// BM=64, BN=128 (full), K=128 (full, in smem). 256 threads, f32x2 packed FMA.
// Math in f32; result rounded to bf16 at store. FMA-issue bound (~105us).
// ---------------------------------------------------------------------------
__global__ __launch_bounds__(256, 2) void proj_kernel(const float* __restrict__ A,
                                                      const float* __restrict__ Watt) {
    extern __shared__ float sm[];
    float (*As)[128] = (float (*)[128])sm;               // [64][128]
    float (*Bs)[128] = (float (*)[128])(sm + 64 * 128);  // [128][128]

    const int half = blockIdx.y;
    const float* W = Watt + half * 128 * 128;
    __nv_bfloat16* P = half ? g_P2 : g_P1;
    const int m0 = blockIdx.x * 64;
    const int tid = threadIdx.x;

#pragma unroll
    for (int i = 0; i < 16; i++) {
        int idx = (tid + i * 256) * 4;
        *(float4*)((float*)Bs + idx) = __ldg((const float4*)(W + idx));
    }
#pragma unroll
    for (int i = 0; i < 8; i++) {
        int idx = (tid + i * 256) * 4;
        int m = idx >> 7;
        int k = idx & 127;
        int gm = m0 + m;
        if (gm >= VOCAB) gm = VOCAB - 1;
        *(float4*)(&As[m][k]) = __ldg((const float4*)(A + (size_t)gm * EMB + k));
    }
    __syncthreads();

    const int tx = tid & 15;
    const int ty = tid >> 4;
    const int mrow = ty * 4;
    const int ncol = tx * 8;

    unsigned long long acc[4][4];
#pragma unroll
    for (int i = 0; i < 4; i++)
#pragma unroll
        for (int j = 0; j < 4; j++) acc[i][j] = 0ull;

#pragma unroll 4
    for (int k0 = 0; k0 < 128; k0 += 4) {
        float4 av[4];
#pragma unroll
        for (int i = 0; i < 4; i++) av[i] = *(const float4*)&As[mrow + i][k0];
#pragma unroll
        for (int kk = 0; kk < 4; kk++) {
            ulonglong2 bq0 = *(const ulonglong2*)&Bs[k0 + kk][ncol];
            ulonglong2 bq1 = *(const ulonglong2*)&Bs[k0 + kk][ncol + 4];
#pragma unroll
            for (int i = 0; i < 4; i++) {
                float a = (kk == 0) ? av[i].x : (kk == 1) ? av[i].y
                         : (kk == 2) ? av[i].z : av[i].w;
                unsigned long long ap;
                asm("mov.b64 %0, {%1, %1};" : "=l"(ap) : "r"(__float_as_uint(a)));
                asm("fma.rn.f32x2 %0, %1, %2, %0;" : "+l"(acc[i][0]) : "l"(ap), "l"(bq0.x));
                asm("fma.rn.f32x2 %0, %1, %2, %0;" : "+l"(acc[i][1]) : "l"(ap), "l"(bq0.y));
                asm("fma.rn.f32x2 %0, %1, %2, %0;" : "+l"(acc[i][2]) : "l"(ap), "l"(bq1.x));
                asm("fma.rn.f32x2 %0, %1, %2, %0;" : "+l"(acc[i][3]) : "l"(ap), "l"(bq1.y));
            }
        }
    }

    // Store: convert 8 f32 (4 f32x2 pairs) -> 4 bf16x2 words -> one 16B store.
#pragma unroll
    for (int i = 0; i < 4; i++) {
        int gm = m0 + mrow + i;
        if (gm < VOCAB) {
            uint4 ov;
            unsigned* po = (unsigned*)&ov;
#pragma unroll
            for (int j = 0; j < 4; j++) {
                float lo = __uint_as_float((unsigned)(acc[i][j] & 0xffffffffull));
                float hi = __uint_as_float((unsigned)(acc[i][j] >> 32));
                asm("cvt.rn.bf16x2.f32 %0, %1, %2;" : "=r"(po[j]) : "f"(hi), "f"(lo));
            }
            *(uint4*)(P + (size_t)gm * EMB + ncol) = ov;
        }
    }
}

// ---------------------------------------------------------------------------
// Attention pass: one warp per code; lane l owns columns [4l, 4l+4).
// __launch_bounds__(256, 2): cap 128 regs -> 2 blocks (16 warps) per SM.
// Liveness is staged so p1v/p2v (32 regs) die before em[] (32 regs) is live.
// ---------------------------------------------------------------------------
__global__ __launch_bounds__(256, 2) void attn_kernel(const float* __restrict__ W_emb,
                                                      const float* __restrict__ b_att,
                                                      const float* __restrict__ v_att,
                                                      const void* __restrict__ leaves,
                                                      const void* __restrict__ ancestors,
                                                      float* __restrict__ out) {
    const int warp = (blockIdx.x * blockDim.x + threadIdx.x) >> 5;
    const int lane = threadIdx.x & 31;
    if (warp >= NCODES) return;
    const int c = lane * 4;
    const int is64 = g_is64;

    const float4 bv = __ldg((const float4*)(b_att + c));
    const float4 vv = __ldg((const float4*)(v_att + c));

    // ---- phase 1: coalesced index row load + shuffle broadcast ----
    // int64 view: row = 16 dwords, lanes 0..15 each load one; value a is at
    // dword 2a (little-endian low word). int32 view: row = 8 dwords, lanes 0..7.
    int wl = 0, wa = 0;
    if (is64) {
        if (lane < 16) {
            const size_t dw = (size_t)warp * 16 + lane;
            wl = __ldg((const int*)leaves + dw);
            wa = __ldg((const int*)ancestors + dw);
        }
    } else {
        if (lane < 8) {
            const size_t dw = (size_t)warp * 8 + lane;
            wl = __ldg((const int*)leaves + dw);
            wa = __ldg((const int*)ancestors + dw);
        }
    }
    const int mul = is64 ? 2 : 1;
    int li[NANC], ai[NANC];
#pragma unroll
    for (int a = 0; a < NANC; a++) {
        li[a] = __shfl_sync(0xffffffffu, wl, a * mul);
        ai[a] = __shfl_sync(0xffffffffu, wa, a * mul);
        li[a] = min(max(li[a], 0), VOCAB - 1);
        ai[a] = min(max(ai[a], 0), VOCAB - 1);
    }

    // ---- phase 2: batch all P1/P2 gathers (bf16: uint2 = 4 values/lane) ----
    uint2 p1v[NANC], p2v[NANC];
#pragma unroll
    for (int a = 0; a < NANC; a++)
        p1v[a] = __ldg((const uint2*)(g_P1 + (size_t)li[a] * EMB + c));
#pragma unroll
    for (int a = 0; a < NANC; a++)
        p2v[a] = __ldg((const uint2*)(g_P2 + (size_t)ai[a] * EMB + c));

    // ---- phase 3: tanh + per-lane partial dots (p1v/p2v die here) ----
    float d[NANC];
#pragma unroll
    for (int a = 0; a < NANC; a++) {
        const float2 p1a = __bfloat1622float2(*(const __nv_bfloat162*)&p1v[a].x);
        const float2 p1b = __bfloat1622float2(*(const __nv_bfloat162*)&p1v[a].y);
        const float2 p2a = __bfloat1622float2(*(const __nv_bfloat162*)&p2v[a].x);
        const float2 p2b = __bfloat1622float2(*(const __nv_bfloat162*)&p2v[a].y);
        const float t0 = tanh_fast(p1a.x + p2a.x + bv.x);
        const float t1 = tanh_fast(p1a.y + p2a.y + bv.y);
        const float t2 = tanh_fast(p1b.x + p2b.x + bv.z);
        const float t3 = tanh_fast(p1b.y + p2b.y + bv.w);
        d[a] = t0 * vv.x + t1 * vv.y + t2 * vv.z + t3 * vv.w;
    }

    // ---- phase 4: batch W_emb gathers (overlap the reduction latency) ----
    float4 em[NANC];
#pragma unroll
    for (int a = 0; a < NANC; a++)
        em[a] = __ldg((const float4*)(W_emb + (size_t)ai[a] * EMB + c));

    // ---- phase 5: parallel butterfly reductions across all 8 scores ----
#pragma unroll
    for (int m = 16; m >= 1; m >>= 1) {
#pragma unroll
        for (int a = 0; a < NANC; a++)
            d[a] += __shfl_xor_sync(0xffffffffu, d[a], m);
    }

    // ---- phase 6: softmax + weighted sum ----
    float mx = d[0];
#pragma unroll
    for (int a = 1; a < NANC; a++) mx = fmaxf(mx, d[a]);
    float sum = 0.0f;
#pragma unroll
    for (int a = 0; a < NANC; a++) { d[a] = __expf(d[a] - mx); sum += d[a]; }
    const float inv = 1.0f / sum;

    float4 accv = make_float4(0.f, 0.f, 0.f, 0.f);
#pragma unroll
    for (int a = 0; a < NANC; a++) {
        const float w = d[a] * inv;
        accv.x += w * em[a].x;
        accv.y += w * em[a].y;
        accv.z += w * em[a].z;
        accv.w += w * em[a].w;
    }
    *(float4*)(out + (size_t)warp * EMB + c) = accv;
}

extern "C" void kernel_launch(void* const* d_in, const int* in_sizes, int n_in,
                              void* d_out, int out_size) {
    // Size-based input identification (robust to metadata ordering).
    const float* W_emb = nullptr;
    const float* W_att = nullptr;
    const float* b_att = nullptr;
    const float* v_att = nullptr;
    const void*  leaves = nullptr;
    const void*  ancestors = nullptr;

    for (int i = 0; i < n_in; i++) {
        const int s = in_sizes[i];
        if (s == VOCAB * EMB)            { W_emb = (const float*)d_in[i]; }
        else if (s == 2 * EMB * EMB)     { W_att = (const float*)d_in[i]; }
        else if (s == EMB)               { if (!b_att) b_att = (const float*)d_in[i];
                                           else        v_att = (const float*)d_in[i]; }
        else if (s == NCODES * NANC)     { if (!leaves) leaves = d_in[i];
                                           else         ancestors = d_in[i]; }
    }
    if (!W_emb)     W_emb     = (const float*)d_in[0];
    if (!W_att)     W_att     = (const float*)d_in[1];
    if (!b_att)     b_att     = (const float*)d_in[2];
    if (!v_att)     v_att     = (const float*)d_in[3];
    if (!leaves)    leaves    = d_in[4];
    if (!ancestors) ancestors = d_in[5];

    float* out = (float*)d_out;

    detect_kernel<<<1, 1024>>>((const unsigned int*)leaves);

    const int smem_bytes = (64 * 128 + 128 * 128) * (int)sizeof(float);  // 96KB
    cudaFuncSetAttribute(proj_kernel, cudaFuncAttributeMaxDynamicSharedMemorySize, smem_bytes);

    dim3 pg((VOCAB + 63) / 64, 2);
    proj_kernel<<<pg, 256, smem_bytes>>>(W_emb, W_att);

    const int total_threads = NCODES * 32;
    attn_kernel<<<(total_threads + 255) / 256, 256>>>(W_emb, b_att, v_att,
                                                      leaves, ancestors, out);
}

// round 11
// speedup vs baseline: 2.3391x; 1.8067x over previous
#include <cuda_runtime.h>
#include <cuda_fp16.h>
#include <cstdint>

#define VOCAB   100000
#define NCODES  100000
#define NANC    8
#define EMB     128

// Projected embeddings in fp16 (score path) + fp16 copy of W_emb (output path).
// Footprint: 26 + 26 + 26 = 78MB -> L2-resident (126MB).
__device__ __align__(16) __half g_P1[(size_t)VOCAB * EMB];
__device__ __align__(16) __half g_P2[(size_t)VOCAB * EMB];
__device__ __align__(16) __half g_E [(size_t)VOCAB * EMB];

__device__ int g_is64;

__device__ __forceinline__ float tanh_fast(float x) {
    float y;
    asm("tanh.approx.f32 %0, %1;" : "=f"(y) : "f"(x));
    return y;
}

// ---------------------------------------------------------------------------
// Dtype detection (sampled): int64 indices < VOCAB have all odd words zero.
// ---------------------------------------------------------------------------
__global__ void detect_kernel(const unsigned int* __restrict__ w) {
    const int half_n = (NCODES * NANC) / 2;
    const int stride = half_n / 2048;          // 195
    int nz = 0;
#pragma unroll
    for (int j = 0; j < 2; j++) {
        int k = (threadIdx.x + j * 1024) * stride;
        nz |= (__ldg(w + 2 * k + 1) != 0u);
    }
    nz = __syncthreads_or(nz);
    if (threadIdx.x == 0) g_is64 = (nz == 0);
}

// ---------------------------------------------------------------------------
// Tensor-core projection: P[half] = W_emb[VOCAB,128] @ W_att[half],  fp16 out.
// BM=128, BN=128, K=128. 256 threads = 8 warps; warp w owns rows [16w,16w+16).
// mma.sync.m16n8k16 f16 inputs / f32 accum (fallback HMMA on sm_103a).
// As: [128][132] fp16 (pad 4).  Bs2: [128][65] u32 = packed {B[2kp][n],B[2kp+1][n]}
// pairs, exactly the b-fragment unit, +1 word pad for bank spread.
// half==0 blocks also emit g_E (the As tile IS fp16 W_emb).
// ---------------------------------------------------------------------------
#define AS_STRIDE 132
#define BS_STRIDE 65

__global__ __launch_bounds__(256) void proj_kernel(const float* __restrict__ A,
                                                   const float* __restrict__ Watt) {
    extern __shared__ char smraw[];
    __half* As  = (__half*)smraw;                          // 128*132*2 = 33792 B
    unsigned* Bs2 = (unsigned*)(smraw + 128 * AS_STRIDE * 2); // 128*65*4 = 33280 B

    const int half = blockIdx.y;
    const float* W = Watt + half * 128 * 128;
    __half* P = half ? g_P2 : g_P1;
    const int m0 = blockIdx.x * 128;
    const int tid = threadIdx.x;
    const int wid = tid >> 5;
    const int lane = tid & 31;

    // ---- stage A (W_emb rows) as fp16: 4096 float4 / 256 thr = 16 each ----
#pragma unroll
    for (int i = 0; i < 16; i++) {
        int e = tid + i * 256;
        int m = e >> 5;
        int kc = (e & 31) * 4;
        int gm = m0 + m; if (gm >= VOCAB) gm = VOCAB - 1;
        float4 v = __ldg((const float4*)(A + (size_t)gm * EMB + kc));
        __half2 h0 = __floats2half2_rn(v.x, v.y);
        __half2 h1 = __floats2half2_rn(v.z, v.w);
        uint2 pk;
        pk.x = *(unsigned*)&h0;
        pk.y = *(unsigned*)&h1;
        *(uint2*)&As[m * AS_STRIDE + kc] = pk;
    }

    // ---- stage B transposed as packed k-pairs: Bs2[n][kp] = {W[2kp][n], W[2kp+1][n]} ----
    // 64 kp-rows handled as: e in [0,2048): kp = e>>5, nc = (e&31)*4  -> 8 iters
#pragma unroll
    for (int i = 0; i < 8; i++) {
        int e = tid + i * 256;
        int kp = e >> 5;
        int nc = (e & 31) * 4;
        float4 v0 = __ldg((const float4*)(W + (size_t)(2 * kp)     * 128 + nc));
        float4 v1 = __ldg((const float4*)(W + (size_t)(2 * kp + 1) * 128 + nc));
        const float* p0 = &v0.x;
        const float* p1 = &v1.x;
#pragma unroll
        for (int j = 0; j < 4; j++) {
            __half2 pr = __floats2half2_rn(p0[j], p1[j]);   // {B[2kp][n], B[2kp+1][n]}
            Bs2[(nc + j) * BS_STRIDE + kp] = *(unsigned*)&pr;
        }
    }
    __syncthreads();

    // ---- emit g_E from the fp16 A tile (half 0 only) ----
    if (half == 0) {
#pragma unroll
        for (int i = 0; i < 16; i++) {
            int e = tid + i * 256;
            int m = e >> 5;
            int kc = (e & 31) * 4;
            int gm = m0 + m;
            if (gm < VOCAB)
                *(uint2*)&g_E[(size_t)gm * EMB + kc] = *(const uint2*)&As[m * AS_STRIDE + kc];
        }
    }

    // ---- mma mainloop ----
    const int g = lane >> 2;          // 0..7
    const int t2 = (lane & 3) * 2;    // 0,2,4,6
    const int w16 = wid * 16;

    float c[16][4];
#pragma unroll
    for (int nt = 0; nt < 16; nt++)
#pragma unroll
        for (int j = 0; j < 4; j++) c[nt][j] = 0.0f;

#pragma unroll
    for (int ks = 0; ks < 8; ks++) {
        const int k0 = ks * 16;
        const unsigned a0 = *(const unsigned*)&As[(w16 + g)     * AS_STRIDE + k0 + t2];
        const unsigned a1 = *(const unsigned*)&As[(w16 + g + 8) * AS_STRIDE + k0 + t2];
        const unsigned a2 = *(const unsigned*)&As[(w16 + g)     * AS_STRIDE + k0 + t2 + 8];
        const unsigned a3 = *(const unsigned*)&As[(w16 + g + 8) * AS_STRIDE + k0 + t2 + 8];
        const int kp0 = (k0 + t2) >> 1;       // = ks*8 + (lane&3)
#pragma unroll
        for (int nt = 0; nt < 16; nt++) {
            const int n = nt * 8 + g;
            const unsigned b0 = Bs2[n * BS_STRIDE + kp0];
            const unsigned b1 = Bs2[n * BS_STRIDE + kp0 + 4];
            asm volatile(
                "mma.sync.aligned.m16n8k16.row.col.f32.f16.f16.f32 "
                "{%0,%1,%2,%3}, {%4,%5,%6,%7}, {%8,%9}, {%0,%1,%2,%3};"
                : "+f"(c[nt][0]), "+f"(c[nt][1]), "+f"(c[nt][2]), "+f"(c[nt][3])
                : "r"(a0), "r"(a1), "r"(a2), "r"(a3), "r"(b0), "r"(b1));
        }
    }

    // ---- epilogue: f32 accum -> fp16 pairs ----
    const int row0 = m0 + w16 + g;
    const int row1 = row0 + 8;
#pragma unroll
    for (int nt = 0; nt < 16; nt++) {
        const int col = nt * 8 + t2;
        if (row0 < VOCAB) {
            __half2 h = __floats2half2_rn(c[nt][0], c[nt][1]);
            *(unsigned*)&P[(size_t)row0 * EMB + col] = *(unsigned*)&h;
        }
        if (row1 < VOCAB) {
            __half2 h = __floats2half2_rn(c[nt][2], c[nt][3]);
            *(unsigned*)&P[(size_t)row1 * EMB + col] = *(unsigned*)&h;
        }
    }
}

// ---------------------------------------------------------------------------
// Attention pass: one warp per code; lane l owns columns [4l, 4l+4).
// All gathers fp16 (8B/lane/row). Output math f32.
// ---------------------------------------------------------------------------
__global__ __launch_bounds__(256, 2) void attn_kernel(const float* __restrict__ b_att,
                                                      const float* __restrict__ v_att,
                                                      const void* __restrict__ leaves,
                                                      const void* __restrict__ ancestors,
                                                      float* __restrict__ out) {
    const int warp = (blockIdx.x * blockDim.x + threadIdx.x) >> 5;
    const int lane = threadIdx.x & 31;
    if (warp >= NCODES) return;
    const int c = lane * 4;
    const int is64 = g_is64;

    const float4 bv = __ldg((const float4*)(b_att + c));
    const float4 vv = __ldg((const float4*)(v_att + c));

    // ---- coalesced index row load + shuffle broadcast ----
    int wl = 0, wa = 0;
    if (is64) {
        if (lane < 16) {
            const size_t dw = (size_t)warp * 16 + lane;
            wl = __ldg((const int*)leaves + dw);
            wa = __ldg((const int*)ancestors + dw);
        }
    } else {
        if (lane < 8) {
            const size_t dw = (size_t)warp * 8 + lane;
            wl = __ldg((const int*)leaves + dw);
            wa = __ldg((const int*)ancestors + dw);
        }
    }
    const int mul = is64 ? 2 : 1;
    int li[NANC], ai[NANC];
#pragma unroll
    for (int a = 0; a < NANC; a++) {
        li[a] = __shfl_sync(0xffffffffu, wl, a * mul);
        ai[a] = __shfl_sync(0xffffffffu, wa, a * mul);
        li[a] = min(max(li[a], 0), VOCAB - 1);
        ai[a] = min(max(ai[a], 0), VOCAB - 1);
    }

    // ---- batch P1/P2 gathers (fp16: uint2 = 4 values/lane) ----
    uint2 p1v[NANC], p2v[NANC];
#pragma unroll
    for (int a = 0; a < NANC; a++)
        p1v[a] = __ldg((const uint2*)(g_P1 + (size_t)li[a] * EMB + c));
#pragma unroll
    for (int a = 0; a < NANC; a++)
        p2v[a] = __ldg((const uint2*)(g_P2 + (size_t)ai[a] * EMB + c));

    // ---- tanh + per-lane partial dots (p1v/p2v die here) ----
    float d[NANC];
#pragma unroll
    for (int a = 0; a < NANC; a++) {
        const float2 p1a = __half22float2(*(const __half2*)&p1v[a].x);
        const float2 p1b = __half22float2(*(const __half2*)&p1v[a].y);
        const float2 p2a = __half22float2(*(const __half2*)&p2v[a].x);
        const float2 p2b = __half22float2(*(const __half2*)&p2v[a].y);
        const float t0 = tanh_fast(p1a.x + p2a.x + bv.x);
        const float t1 = tanh_fast(p1a.y + p2a.y + bv.y);
        const float t2 = tanh_fast(p1b.x + p2b.x + bv.z);
        const float t3 = tanh_fast(p1b.y + p2b.y + bv.w);
        d[a] = t0 * vv.x + t1 * vv.y + t2 * vv.z + t3 * vv.w;
    }

    // ---- batch fp16 embedding gathers (overlap reduction latency) ----
    uint2 ev[NANC];
#pragma unroll
    for (int a = 0; a < NANC; a++)
        ev[a] = __ldg((const uint2*)(g_E + (size_t)ai[a] * EMB + c));

    // ---- parallel butterfly reductions across all 8 scores ----
#pragma unroll
    for (int m = 16; m >= 1; m >>= 1) {
#pragma unroll
        for (int a = 0; a < NANC; a++)
            d[a] += __shfl_xor_sync(0xffffffffu, d[a], m);
    }

    // ---- softmax + weighted sum ----
    float mx = d[0];
#pragma unroll
    for (int a = 1; a < NANC; a++) mx = fmaxf(mx, d[a]);
    float sum = 0.0f;
#pragma unroll
    for (int a = 0; a < NANC; a++) { d[a] = __expf(d[a] - mx); sum += d[a]; }
    const float inv = 1.0f / sum;

    float4 accv = make_float4(0.f, 0.f, 0.f, 0.f);
#pragma unroll
    for (int a = 0; a < NANC; a++) {
        const float w = d[a] * inv;
        const float2 ea = __half22float2(*(const __half2*)&ev[a].x);
        const float2 eb = __half22float2(*(const __half2*)&ev[a].y);
        accv.x += w * ea.x;
        accv.y += w * ea.y;
        accv.z += w * eb.x;
        accv.w += w * eb.y;
    }
    *(float4*)(out + (size_t)warp * EMB + c) = accv;
}

extern "C" void kernel_launch(void* const* d_in, const int* in_sizes, int n_in,
                              void* d_out, int out_size) {
    const float* W_emb = nullptr;
    const float* W_att = nullptr;
    const float* b_att = nullptr;
    const float* v_att = nullptr;
    const void*  leaves = nullptr;
    const void*  ancestors = nullptr;

    for (int i = 0; i < n_in; i++) {
        const int s = in_sizes[i];
        if (s == VOCAB * EMB)            { W_emb = (const float*)d_in[i]; }
        else if (s == 2 * EMB * EMB)     { W_att = (const float*)d_in[i]; }
        else if (s == EMB)               { if (!b_att) b_att = (const float*)d_in[i];
                                           else        v_att = (const float*)d_in[i]; }
        else if (s == NCODES * NANC)     { if (!leaves) leaves = d_in[i];
                                           else         ancestors = d_in[i]; }
    }
    if (!W_emb)     W_emb     = (const float*)d_in[0];
    if (!W_att)     W_att     = (const float*)d_in[1];
    if (!b_att)     b_att     = (const float*)d_in[2];
    if (!v_att)     v_att     = (const float*)d_in[3];
    if (!leaves)    leaves    = d_in[4];
    if (!ancestors) ancestors = d_in[5];

    float* out = (float*)d_out;

    detect_kernel<<<1, 1024>>>((const unsigned int*)leaves);

    const int smem_bytes = 128 * AS_STRIDE * 2 + 128 * BS_STRIDE * 4;  // 67072 B
    cudaFuncSetAttribute(proj_kernel, cudaFuncAttributeMaxDynamicSharedMemorySize, smem_bytes);

    dim3 pg((VOCAB + 127) / 128, 2);
    proj_kernel<<<pg, 256, smem_bytes>>>(W_emb, W_att);

    const int total_threads = NCODES * 32;
    attn_kernel<<<(total_threads + 255) / 256, 256>>>(b_att, v_att,
                                                      leaves, ancestors, out);
}

// round 12
// speedup vs baseline: 2.4718x; 1.0568x over previous
#include <cuda_runtime.h>
#include <cuda_fp16.h>
#include <cstdint>

#define VOCAB   100000
#define NCODES  100000
#define NANC    8
#define EMB     128

// Projected embeddings in fp16 (score path) + fp16 copy of W_emb (output path).
// Footprint: 26 + 26 + 26 = 78MB -> L2-resident (126MB).
__device__ __align__(16) __half g_P1[(size_t)VOCAB * EMB];
__device__ __align__(16) __half g_P2[(size_t)VOCAB * EMB];
__device__ __align__(16) __half g_E [(size_t)VOCAB * EMB];

__device__ __forceinline__ float tanh_fast(float x) {
    float y;
    asm("tanh.approx.f32 %0, %1;" : "=f"(y) : "f"(x));
    return y;
}

// ---------------------------------------------------------------------------
// Tensor-core projection: P[half] = W_emb[VOCAB,128] @ W_att[half],  fp16 out.
// BM=128, BN=128, K=128. 256 threads = 8 warps; warp w owns rows [16w,16w+16).
// mma.sync.m16n8k16 f16/f32. half==0 blocks also emit g_E (fp16 W_emb tile).
// ---------------------------------------------------------------------------
#define AS_STRIDE 132
#define BS_STRIDE 65

__global__ __launch_bounds__(256) void proj_kernel(const float* __restrict__ A,
                                                   const float* __restrict__ Watt) {
    extern __shared__ char smraw[];
    __half* As  = (__half*)smraw;                             // 128*132*2 B
    unsigned* Bs2 = (unsigned*)(smraw + 128 * AS_STRIDE * 2); // 128*65*4 B

    const int half = blockIdx.y;
    const float* W = Watt + half * 128 * 128;
    __half* P = half ? g_P2 : g_P1;
    const int m0 = blockIdx.x * 128;
    const int tid = threadIdx.x;
    const int wid = tid >> 5;
    const int lane = tid & 31;

    // ---- stage A (W_emb rows) as fp16 ----
#pragma unroll
    for (int i = 0; i < 16; i++) {
        int e = tid + i * 256;
        int m = e >> 5;
        int kc = (e & 31) * 4;
        int gm = m0 + m; if (gm >= VOCAB) gm = VOCAB - 1;
        float4 v = __ldg((const float4*)(A + (size_t)gm * EMB + kc));
        __half2 h0 = __floats2half2_rn(v.x, v.y);
        __half2 h1 = __floats2half2_rn(v.z, v.w);
        uint2 pk;
        pk.x = *(unsigned*)&h0;
        pk.y = *(unsigned*)&h1;
        *(uint2*)&As[m * AS_STRIDE + kc] = pk;
    }

    // ---- stage B transposed as packed k-pairs ----
#pragma unroll
    for (int i = 0; i < 8; i++) {
        int e = tid + i * 256;
        int kp = e >> 5;
        int nc = (e & 31) * 4;
        float4 v0 = __ldg((const float4*)(W + (size_t)(2 * kp)     * 128 + nc));
        float4 v1 = __ldg((const float4*)(W + (size_t)(2 * kp + 1) * 128 + nc));
        const float* p0 = &v0.x;
        const float* p1 = &v1.x;
#pragma unroll
        for (int j = 0; j < 4; j++) {
            __half2 pr = __floats2half2_rn(p0[j], p1[j]);
            Bs2[(nc + j) * BS_STRIDE + kp] = *(unsigned*)&pr;
        }
    }
    __syncthreads();

    // ---- emit g_E from the fp16 A tile (half 0 only) ----
    if (half == 0) {
#pragma unroll
        for (int i = 0; i < 16; i++) {
            int e = tid + i * 256;
            int m = e >> 5;
            int kc = (e & 31) * 4;
            int gm = m0 + m;
            if (gm < VOCAB)
                *(uint2*)&g_E[(size_t)gm * EMB + kc] = *(const uint2*)&As[m * AS_STRIDE + kc];
        }
    }

    // ---- mma mainloop ----
    const int g = lane >> 2;
    const int t2 = (lane & 3) * 2;
    const int w16 = wid * 16;

    float c[16][4];
#pragma unroll
    for (int nt = 0; nt < 16; nt++)
#pragma unroll
        for (int j = 0; j < 4; j++) c[nt][j] = 0.0f;

#pragma unroll
    for (int ks = 0; ks < 8; ks++) {
        const int k0 = ks * 16;
        const unsigned a0 = *(const unsigned*)&As[(w16 + g)     * AS_STRIDE + k0 + t2];
        const unsigned a1 = *(const unsigned*)&As[(w16 + g + 8) * AS_STRIDE + k0 + t2];
        const unsigned a2 = *(const unsigned*)&As[(w16 + g)     * AS_STRIDE + k0 + t2 + 8];
        const unsigned a3 = *(const unsigned*)&As[(w16 + g + 8) * AS_STRIDE + k0 + t2 + 8];
        const int kp0 = (k0 + t2) >> 1;
#pragma unroll
        for (int nt = 0; nt < 16; nt++) {
            const int n = nt * 8 + g;
            const unsigned b0 = Bs2[n * BS_STRIDE + kp0];
            const unsigned b1 = Bs2[n * BS_STRIDE + kp0 + 4];
            asm volatile(
                "mma.sync.aligned.m16n8k16.row.col.f32.f16.f16.f32 "
                "{%0,%1,%2,%3}, {%4,%5,%6,%7}, {%8,%9}, {%0,%1,%2,%3};"
                : "+f"(c[nt][0]), "+f"(c[nt][1]), "+f"(c[nt][2]), "+f"(c[nt][3])
                : "r"(a0), "r"(a1), "r"(a2), "r"(a3), "r"(b0), "r"(b1));
        }
    }

    // ---- epilogue: f32 accum -> fp16 pairs ----
    const int row0 = m0 + w16 + g;
    const int row1 = row0 + 8;
#pragma unroll
    for (int nt = 0; nt < 16; nt++) {
        const int col = nt * 8 + t2;
        if (row0 < VOCAB) {
            __half2 h = __floats2half2_rn(c[nt][0], c[nt][1]);
            *(unsigned*)&P[(size_t)row0 * EMB + col] = *(unsigned*)&h;
        }
        if (row1 < VOCAB) {
            __half2 h = __floats2half2_rn(c[nt][2], c[nt][3]);
            *(unsigned*)&P[(size_t)row1 * EMB + col] = *(unsigned*)&h;
        }
    }
}

// ---------------------------------------------------------------------------
// Attention pass: one warp per code; lane l owns columns [4l, 4l+4).
// Self-detecting index dtype (no separate detect kernel):
//   probe = dwords [warp*8, warp*8+8), in-bounds under BOTH interpretations.
//   int64 data < VOCAB  => all odd probe dwords are zero (high words).
//   int32 data          => odd probe dwords are random indices; all-zero
//                          probability (1e-5)^16 across both tables ~ 0.
// 128-thread blocks, min 5 blocks/SM -> 20 warps/SM.
// ---------------------------------------------------------------------------
__global__ __launch_bounds__(128, 5) void attn_kernel(const float* __restrict__ b_att,
                                                      const float* __restrict__ v_att,
                                                      const void* __restrict__ leaves,
                                                      const void* __restrict__ ancestors,
                                                      float* __restrict__ out) {
    const int warp = (blockIdx.x * blockDim.x + threadIdx.x) >> 5;
    const int lane = threadIdx.x & 31;
    if (warp >= NCODES) return;
    const int c = lane * 4;

    const float4 bv = __ldg((const float4*)(b_att + c));
    const float4 vv = __ldg((const float4*)(v_att + c));

    // ---- phase 1a: bounded probe + dtype ballot ----
    int pl = 0, pa = 0;
    if (lane < 8) {
        const size_t dw = (size_t)warp * 8 + lane;
        pl = __ldg((const int*)leaves + dw);
        pa = __ldg((const int*)ancestors + dw);
    }
    const unsigned bl = __ballot_sync(0xffffffffu, pl != 0);
    const unsigned ba = __ballot_sync(0xffffffffu, pa != 0);
    const bool is64 = (((bl | ba) & 0xAAu) == 0u);   // odd lanes 1,3,5,7 all zero

    // ---- phase 1b: index row fetch + shuffle broadcast ----
    int wl, wa, mul;
    if (is64) {
        wl = 0; wa = 0;
        if (lane < 16) {
            const size_t dw = (size_t)warp * 16 + lane;   // safe: buffer is 1.6M dwords
            wl = __ldg((const int*)leaves + dw);
            wa = __ldg((const int*)ancestors + dw);
        }
        mul = 2;
    } else {
        wl = pl; wa = pa;                                  // probe WAS the int32 row
        mul = 1;
    }
    int li[NANC], ai[NANC];
#pragma unroll
    for (int a = 0; a < NANC; a++) {
        li[a] = __shfl_sync(0xffffffffu, wl, a * mul);
        ai[a] = __shfl_sync(0xffffffffu, wa, a * mul);
        li[a] = min(max(li[a], 0), VOCAB - 1);
        ai[a] = min(max(ai[a], 0), VOCAB - 1);
    }

    // ---- phase 2: issue ALL 24 gathers back-to-back (max MLP) ----
    uint2 p1v[NANC], p2v[NANC], ev[NANC];
#pragma unroll
    for (int a = 0; a < NANC; a++)
        p1v[a] = __ldg((const uint2*)(g_P1 + (size_t)li[a] * EMB + c));
#pragma unroll
    for (int a = 0; a < NANC; a++)
        p2v[a] = __ldg((const uint2*)(g_P2 + (size_t)ai[a] * EMB + c));
#pragma unroll
    for (int a = 0; a < NANC; a++)
        ev[a] = __ldg((const uint2*)(g_E + (size_t)ai[a] * EMB + c));

    // ---- phase 3: tanh + per-lane partial dots ----
    float d[NANC];
#pragma unroll
    for (int a = 0; a < NANC; a++) {
        const float2 p1a = __half22float2(*(const __half2*)&p1v[a].x);
        const float2 p1b = __half22float2(*(const __half2*)&p1v[a].y);
        const float2 p2a = __half22float2(*(const __half2*)&p2v[a].x);
        const float2 p2b = __half22float2(*(const __half2*)&p2v[a].y);
        const float t0 = tanh_fast(p1a.x + p2a.x + bv.x);
        const float t1 = tanh_fast(p1a.y + p2a.y + bv.y);
        const float t2 = tanh_fast(p1b.x + p2b.x + bv.z);
        const float t3 = tanh_fast(p1b.y + p2b.y + bv.w);
        d[a] = t0 * vv.x + t1 * vv.y + t2 * vv.z + t3 * vv.w;
    }

    // ---- phase 4: parallel butterfly reductions ----
#pragma unroll
    for (int m = 16; m >= 1; m >>= 1) {
#pragma unroll
        for (int a = 0; a < NANC; a++)
            d[a] += __shfl_xor_sync(0xffffffffu, d[a], m);
    }

    // ---- phase 5: softmax + weighted sum ----
    float mx = d[0];
#pragma unroll
    for (int a = 1; a < NANC; a++) mx = fmaxf(mx, d[a]);
    float sum = 0.0f;
#pragma unroll
    for (int a = 0; a < NANC; a++) { d[a] = __expf(d[a] - mx); sum += d[a]; }
    const float inv = 1.0f / sum;

    float4 accv = make_float4(0.f, 0.f, 0.f, 0.f);
#pragma unroll
    for (int a = 0; a < NANC; a++) {
        const float w = d[a] * inv;
        const float2 ea = __half22float2(*(const __half2*)&ev[a].x);
        const float2 eb = __half22float2(*(const __half2*)&ev[a].y);
        accv.x += w * ea.x;
        accv.y += w * ea.y;
        accv.z += w * eb.x;
        accv.w += w * eb.y;
    }
    *(float4*)(out + (size_t)warp * EMB + c) = accv;
}

extern "C" void kernel_launch(void* const* d_in, const int* in_sizes, int n_in,
                              void* d_out, int out_size) {
    const float* W_emb = nullptr;
    const float* W_att = nullptr;
    const float* b_att = nullptr;
    const float* v_att = nullptr;
    const void*  leaves = nullptr;
    const void*  ancestors = nullptr;

    for (int i = 0; i < n_in; i++) {
        const int s = in_sizes[i];
        if (s == VOCAB * EMB)            { W_emb = (const float*)d_in[i]; }
        else if (s == 2 * EMB * EMB)     { W_att = (const float*)d_in[i]; }
        else if (s == EMB)               { if (!b_att) b_att = (const float*)d_in[i];
                                           else        v_att = (const float*)d_in[i]; }
        else if (s == NCODES * NANC)     { if (!leaves) leaves = d_in[i];
                                           else         ancestors = d_in[i]; }
    }
    if (!W_emb)     W_emb     = (const float*)d_in[0];
    if (!W_att)     W_att     = (const float*)d_in[1];
    if (!b_att)     b_att     = (const float*)d_in[2];
    if (!v_att)     v_att     = (const float*)d_in[3];
    if (!leaves)    leaves    = d_in[4];
    if (!ancestors) ancestors = d_in[5];

    float* out = (float*)d_out;

    const int smem_bytes = 128 * AS_STRIDE * 2 + 128 * BS_STRIDE * 4;  // 67072 B
    cudaFuncSetAttribute(proj_kernel, cudaFuncAttributeMaxDynamicSharedMemorySize, smem_bytes);

    dim3 pg((VOCAB + 127) / 128, 2);
    proj_kernel<<<pg, 256, smem_bytes>>>(W_emb, W_att);

    const int total_threads = NCODES * 32;
    attn_kernel<<<(total_threads + 127) / 128, 128>>>(b_att, v_att,
                                                      leaves, ancestors, out);
}

// round 14
// speedup vs baseline: 3.2539x; 1.3164x over previous
#include <cuda_runtime.h>
#include <cuda_fp16.h>
#include <cstdint>

#define VOCAB   100000
#define NCODES  100000
#define NANC    8
#define EMB     128

// fp16 projected embeddings + fp16 W_emb copy. 78MB -> L2-resident.
__device__ __align__(16) __half g_P1[(size_t)VOCAB * EMB];
__device__ __align__(16) __half g_P2[(size_t)VOCAB * EMB];
__device__ __align__(16) __half g_E [(size_t)VOCAB * EMB];

__device__ __forceinline__ float tanh_fast(float x) {
    float y;
    asm("tanh.approx.f32 %0, %1;" : "=f"(y) : "f"(x));
    return y;
}

// ---------------------------------------------------------------------------
// Fused projection (mma.sync HMMA path -- tcgen05 ISA is unavailable under
// the harness's .target sm_103):
//   P1 = W_emb @ W_att[0:128],  P2 = W_emb @ W_att[128:256], g_E = fp16(W_emb)
// One block per 64 rows; 8 warps: warps 0-3 half 0, warps 4-7 half 1,
// warp (w&3) owns rows [16(w&3), 16(w&3)+16). A staged ONCE per tile.
//
// SMEM:
//   As  [64][132] fp16                    (16896 B)
//   Bp  [2][32][132] uint2                (67584 B)
//     Bp[h][j][n] = { pack(W[h*128+2*kpa][n], W[h*128+2*kpa+1][n]),
//                     pack(W[h*128+2*kpb][n], W[h*128+2*kpb+1][n]) }
//     with kpa = (j>>2)*8 + (j&3), kpb = kpa + 4
//   => the exact m16n8k16 b-fragment {b0,b1} for (ks=j>>2, q=j&3) in ONE
//      8B LDS; j-major stride-132 keeps conflicts <= 2-way.
// ---------------------------------------------------------------------------
#define AS_STRIDE 132
#define BP_STRIDE 132
#define SM_AS_BYTES (64 * AS_STRIDE * 2)
#define SM_TOT      (SM_AS_BYTES + 2 * 32 * BP_STRIDE * 8)

__global__ __launch_bounds__(256) void proj_kernel(const float* __restrict__ A,
                                                   const float* __restrict__ Watt) {
    extern __shared__ char smraw[];
    __half* As = (__half*)smraw;
    uint2*  Bp = (uint2*)(smraw + SM_AS_BYTES);

    const int m0 = blockIdx.x * 64;
    const int tid = threadIdx.x;
    const int wid = tid >> 5;
    const int lane = tid & 31;

    // ---- stage A (64 rows) as fp16 + emit g_E (free) ----
#pragma unroll
    for (int i = 0; i < 8; i++) {
        int e = tid + i * 256;          // [0, 2048)
        int m = e >> 5;
        int kc = (e & 31) * 4;
        int gm = m0 + m; if (gm >= VOCAB) gm = VOCAB - 1;
        float4 v = __ldg((const float4*)(A + (size_t)gm * EMB + kc));
        __half2 h0 = __floats2half2_rn(v.x, v.y);
        __half2 h1 = __floats2half2_rn(v.z, v.w);
        uint2 pk; pk.x = *(unsigned*)&h0; pk.y = *(unsigned*)&h1;
        *(uint2*)&As[m * AS_STRIDE + kc] = pk;
        if (m0 + m < VOCAB)
            *(uint2*)&g_E[(size_t)(m0 + m) * EMB + kc] = pk;
    }

    // ---- stage B fragment pairs for both halves ----
#pragma unroll
    for (int i = 0; i < 32; i++) {
        int e = tid + i * 256;          // [0, 8192)
        int h   = e >> 12;
        int rem = e & 4095;
        int j   = rem >> 7;             // 0..31
        int n   = rem & 127;            // lanes -> consecutive n (coalesced)
        int kpa = (j >> 2) * 8 + (j & 3);
        const float* Wh = Watt + (size_t)h * 128 * 128;
        float w0 = __ldg(Wh + (size_t)(2 * kpa)     * 128 + n);
        float w1 = __ldg(Wh + (size_t)(2 * kpa + 1) * 128 + n);
        float w2 = __ldg(Wh + (size_t)(2 * kpa + 8) * 128 + n);   // kpb = kpa+4
        float w3 = __ldg(Wh + (size_t)(2 * kpa + 9) * 128 + n);
        __half2 ha = __floats2half2_rn(w0, w1);
        __half2 hb = __floats2half2_rn(w2, w3);
        uint2 pr; pr.x = *(unsigned*)&ha; pr.y = *(unsigned*)&hb;
        Bp[(h * 32 + j) * BP_STRIDE + n] = pr;
    }
    __syncthreads();

    // ---- mma mainloop ----
    const int g = lane >> 2;          // 0..7
    const int q = lane & 3;
    const int t2 = q * 2;
    const int half = wid >> 2;
    const int w16 = (wid & 3) * 16;
    const uint2* BpH = Bp + half * 32 * BP_STRIDE;

    float c[16][4];
#pragma unroll
    for (int nt = 0; nt < 16; nt++)
#pragma unroll
        for (int j = 0; j < 4; j++) c[nt][j] = 0.0f;

#pragma unroll
    for (int ks = 0; ks < 8; ks++) {
        const int k0 = ks * 16;
        const unsigned a0 = *(const unsigned*)&As[(w16 + g)     * AS_STRIDE + k0 + t2];
        const unsigned a1 = *(const unsigned*)&As[(w16 + g + 8) * AS_STRIDE + k0 + t2];
        const unsigned a2 = *(const unsigned*)&As[(w16 + g)     * AS_STRIDE + k0 + t2 + 8];
        const unsigned a3 = *(const unsigned*)&As[(w16 + g + 8) * AS_STRIDE + k0 + t2 + 8];
        const uint2* brow = BpH + (ks * 4 + q) * BP_STRIDE;
#pragma unroll
        for (int nt = 0; nt < 16; nt++) {
            const uint2 b = brow[nt * 8 + g];
            asm volatile(
                "mma.sync.aligned.m16n8k16.row.col.f32.f16.f16.f32 "
                "{%0,%1,%2,%3}, {%4,%5,%6,%7}, {%8,%9}, {%0,%1,%2,%3};"
                : "+f"(c[nt][0]), "+f"(c[nt][1]), "+f"(c[nt][2]), "+f"(c[nt][3])
                : "r"(a0), "r"(a1), "r"(a2), "r"(a3), "r"(b.x), "r"(b.y));
        }
    }

    // ---- epilogue: f32 accum -> fp16 pairs ----
    __half* P = half ? g_P2 : g_P1;
    const int row0 = m0 + w16 + g;
    const int row1 = row0 + 8;
#pragma unroll
    for (int nt = 0; nt < 16; nt++) {
        const int col = nt * 8 + t2;
        if (row0 < VOCAB) {
            __half2 h = __floats2half2_rn(c[nt][0], c[nt][1]);
            *(unsigned*)&P[(size_t)row0 * EMB + col] = *(unsigned*)&h;
        }
        if (row1 < VOCAB) {
            __half2 h = __floats2half2_rn(c[nt][2], c[nt][3]);
            *(unsigned*)&P[(size_t)row1 * EMB + col] = *(unsigned*)&h;
        }
    }
}

// ---------------------------------------------------------------------------
// Attention pass (frozen from R12: 63.4us, issue-bound): one warp per code,
// self-detecting index dtype, 24 batched gathers.
// ---------------------------------------------------------------------------
__global__ __launch_bounds__(128, 5) void attn_kernel(const float* __restrict__ b_att,
                                                      const float* __restrict__ v_att,
                                                      const void* __restrict__ leaves,
                                                      const void* __restrict__ ancestors,
                                                      float* __restrict__ out) {
    const int warp = (blockIdx.x * blockDim.x + threadIdx.x) >> 5;
    const int lane = threadIdx.x & 31;
    if (warp >= NCODES) return;
    const int c = lane * 4;

    const float4 bv = __ldg((const float4*)(b_att + c));
    const float4 vv = __ldg((const float4*)(v_att + c));

    int pl = 0, pa = 0;
    if (lane < 8) {
        const size_t dw = (size_t)warp * 8 + lane;
        pl = __ldg((const int*)leaves + dw);
        pa = __ldg((const int*)ancestors + dw);
    }
    const unsigned bl = __ballot_sync(0xffffffffu, pl != 0);
    const unsigned ba = __ballot_sync(0xffffffffu, pa != 0);
    const bool is64 = (((bl | ba) & 0xAAu) == 0u);

    int wl, wa, mul;
    if (is64) {
        wl = 0; wa = 0;
        if (lane < 16) {
            const size_t dw = (size_t)warp * 16 + lane;
            wl = __ldg((const int*)leaves + dw);
            wa = __ldg((const int*)ancestors + dw);
        }
        mul = 2;
    } else {
        wl = pl; wa = pa; mul = 1;
    }
    int li[NANC], ai[NANC];
#pragma unroll
    for (int a = 0; a < NANC; a++) {
        li[a] = __shfl_sync(0xffffffffu, wl, a * mul);
        ai[a] = __shfl_sync(0xffffffffu, wa, a * mul);
        li[a] = min(max(li[a], 0), VOCAB - 1);
        ai[a] = min(max(ai[a], 0), VOCAB - 1);
    }

    uint2 p1v[NANC], p2v[NANC], ev[NANC];
#pragma unroll
    for (int a = 0; a < NANC; a++)
        p1v[a] = __ldg((const uint2*)(g_P1 + (size_t)li[a] * EMB + c));
#pragma unroll
    for (int a = 0; a < NANC; a++)
        p2v[a] = __ldg((const uint2*)(g_P2 + (size_t)ai[a] * EMB + c));
#pragma unroll
    for (int a = 0; a < NANC; a++)
        ev[a] = __ldg((const uint2*)(g_E + (size_t)ai[a] * EMB + c));

    float d[NANC];
#pragma unroll
    for (int a = 0; a < NANC; a++) {
        const float2 p1a = __half22float2(*(const __half2*)&p1v[a].x);
        const float2 p1b = __half22float2(*(const __half2*)&p1v[a].y);
        const float2 p2a = __half22float2(*(const __half2*)&p2v[a].x);
        const float2 p2b = __half22float2(*(const __half2*)&p2v[a].y);
        const float t0 = tanh_fast(p1a.x + p2a.x + bv.x);
        const float t1 = tanh_fast(p1a.y + p2a.y + bv.y);
        const float t2 = tanh_fast(p1b.x + p2b.x + bv.z);
        const float t3 = tanh_fast(p1b.y + p2b.y + bv.w);
        d[a] = t0 * vv.x + t1 * vv.y + t2 * vv.z + t3 * vv.w;
    }

#pragma unroll
    for (int m = 16; m >= 1; m >>= 1) {
#pragma unroll
        for (int a = 0; a < NANC; a++)
            d[a] += __shfl_xor_sync(0xffffffffu, d[a], m);
    }

    float mx = d[0];
#pragma unroll
    for (int a = 1; a < NANC; a++) mx = fmaxf(mx, d[a]);
    float sum = 0.0f;
#pragma unroll
    for (int a = 0; a < NANC; a++) { d[a] = __expf(d[a] - mx); sum += d[a]; }
    const float inv = 1.0f / sum;

    float4 accv = make_float4(0.f, 0.f, 0.f, 0.f);
#pragma unroll
    for (int a = 0; a < NANC; a++) {
        const float w = d[a] * inv;
        const float2 ea = __half22float2(*(const __half2*)&ev[a].x);
        const float2 eb = __half22float2(*(const __half2*)&ev[a].y);
        accv.x += w * ea.x;
        accv.y += w * ea.y;
        accv.z += w * eb.x;
        accv.w += w * eb.y;
    }
    *(float4*)(out + (size_t)warp * EMB + c) = accv;
}

extern "C" void kernel_launch(void* const* d_in, const int* in_sizes, int n_in,
                              void* d_out, int out_size) {
    const float* W_emb = nullptr;
    const float* W_att = nullptr;
    const float* b_att = nullptr;
    const float* v_att = nullptr;
    const void*  leaves = nullptr;
    const void*  ancestors = nullptr;

    for (int i = 0; i < n_in; i++) {
        const int s = in_sizes[i];
        if (s == VOCAB * EMB)            { W_emb = (const float*)d_in[i]; }
        else if (s == 2 * EMB * EMB)     { W_att = (const float*)d_in[i]; }
        else if (s == EMB)               { if (!b_att) b_att = (const float*)d_in[i];
                                           else        v_att = (const float*)d_in[i]; }
        else if (s == NCODES * NANC)     { if (!leaves) leaves = d_in[i];
                                           else         ancestors = d_in[i]; }
    }
    if (!W_emb)     W_emb     = (const float*)d_in[0];
    if (!W_att)     W_att     = (const float*)d_in[1];
    if (!b_att)     b_att     = (const float*)d_in[2];
    if (!v_att)     v_att     = (const float*)d_in[3];
    if (!leaves)    leaves    = d_in[4];
    if (!ancestors) ancestors = d_in[5];

    float* out = (float*)d_out;

    cudaFuncSetAttribute(proj_kernel, cudaFuncAttributeMaxDynamicSharedMemorySize, SM_TOT);
    proj_kernel<<<(VOCAB + 63) / 64, 256, SM_TOT>>>(W_emb, W_att);

    const int total_threads = NCODES * 32;
    attn_kernel<<<(total_threads + 127) / 128, 128>>>(b_att, v_att,
                                                      leaves, ancestors, out);
}